// round 9
// baseline (speedup 1.0000x reference)
#include <cuda_runtime.h>
#include <cuda_bf16.h>
#include <stdint.h>
#include <math.h>

#define CD 128
#define NMAX 100352
#define EMAX 1700000

// ---------------- device scratch ----------------
__device__ __align__(16) float g_P[(size_t)NMAX * CD];      // fp32 logits OR bf16 conv out
__device__ __align__(16) float g_H[(size_t)NMAX * CD / 2];  // bf16 hidden
__device__ float g_dis[NMAX];
__device__ int   g_cnt[NMAX];
__device__ int   g_off[NMAX];
__device__ int   g_cur[NMAX];
__device__ int   g_bkt[EMAX];
__device__ int   g_part[128];
__device__ __align__(16) __nv_bfloat16 g_Wb[3][CD * CD];    // bf16 W[c_out][c_in]

__device__ __forceinline__ unsigned int pack_bf16x2(float lo, float hi) {
    unsigned int r;
    asm("cvt.rn.bf16x2.f32 %0, %1, %2;" : "=r"(r) : "f"(hi), "f"(lo));
    return r;
}

// ---------------- init: zero cnt + convert all three weights ----------------
__global__ void k_init(const float* __restrict__ W1, const float* __restrict__ W2,
                       const float* __restrict__ Wl, int n) {
    int i = blockIdx.x * blockDim.x + threadIdx.x;
    if (i < n) g_cnt[i] = 0;
    if (i < 3 * 16384) {
        int which = i >> 14, j = i & 16383;
        const float* W = (which == 0) ? W1 : (which == 1) ? W2 : Wl;
        g_Wb[which][j] = __float2bfloat16(W[j]);
    }
}

// ---------------- scan (dis fused) ----------------
__global__ void k_scan1(int n) {
    __shared__ int wsum[32];
    int tid = threadIdx.x;
    int lane = tid & 31, wid = tid >> 5;
    int i = blockIdx.x * 1024 + tid;
    int x = (i < n) ? g_cnt[i] : 0;
    if (i < n) g_dis[i] = rsqrtf((float)x + 1.0f);
    int v = x;
#pragma unroll
    for (int d = 1; d < 32; d <<= 1) {
        int t = __shfl_up_sync(0xFFFFFFFFu, v, d);
        if (lane >= d) v += t;
    }
    if (lane == 31) wsum[wid] = v;
    __syncthreads();
    if (wid == 0) {
        int w = wsum[lane];
#pragma unroll
        for (int d = 1; d < 32; d <<= 1) {
            int t = __shfl_up_sync(0xFFFFFFFFu, w, d);
            if (lane >= d) w += t;
        }
        wsum[lane] = w;
    }
    __syncthreads();
    int base = (wid > 0) ? wsum[wid - 1] : 0;
    if (i < n) g_off[i] = base + v - x;
    if (tid == 1023) g_part[blockIdx.x] = wsum[31];
}

__global__ void k_scan2(int nb) {
    __shared__ int s[128];
    int tid = threadIdx.x;
    int x = (tid < nb) ? g_part[tid] : 0;
    s[tid] = x;
    __syncthreads();
    for (int d = 1; d < 128; d <<= 1) {
        int t = (tid >= d) ? s[tid - d] : 0;
        __syncthreads();
        s[tid] += t;
        __syncthreads();
    }
    if (tid < nb) g_part[tid] = s[tid] - x;
}

__global__ void k_scan3(int n) {
    int i = blockIdx.x * blockDim.x + threadIdx.x;
    if (i < n) {
        int v = g_off[i] + g_part[i >> 10];
        g_off[i] = v;
        g_cur[i] = v;
    }
}

__global__ void k_fill(const int* __restrict__ row, const int* __restrict__ col, int E) {
    for (int e = blockIdx.x * blockDim.x + threadIdx.x; e < E;
         e += gridDim.x * blockDim.x) {
        int p = atomicAdd(&g_cur[col[e]], 1);
        g_bkt[p] = row[e];
    }
}

// ---------------- bf16 tensor-core GEMM (+optional count tail blocks) ---------------
// Blocks [0, gemmB): P[i][c] = scale? * sum_k X[i][k] * W[c][k]  (m16n8k16 bf16 MMA)
//   useDis=0: raw output (conv1 — dis not yet computed; gather applies it per-row)
//   useDis=1: epilogue scales rows by g_dis (conv2 — dis valid)
// Blocks [gemmB, gridDim): grid-stride degree count over col[] (conv1 launch only)
__global__ void __launch_bounds__(256)
k_gemm_bf16(const float* __restrict__ Xf, int useXf, int widx, int useDis, int outF32,
            int n, int gemmB, const int* __restrict__ colE, int E) {
    if (blockIdx.x >= gemmB) {          // count-mode tail blocks (overlapped preproc)
        int nb = gridDim.x - gemmB;
        for (int e = (blockIdx.x - gemmB) * blockDim.x + threadIdx.x; e < E;
             e += nb * blockDim.x)
            atomicAdd(&g_cnt[colE[e]], 1);
        return;
    }

    __shared__ __align__(16) __nv_bfloat16 Xs[128][72];
    __shared__ __align__(16) __nv_bfloat16 Ws[128][72];

    const __nv_bfloat16* __restrict__ Hb = (const __nv_bfloat16*)g_H;
    const __nv_bfloat16* __restrict__ Wb = g_Wb[widx];

    int row0 = blockIdx.x * 128;
    int tid = threadIdx.x;
    int wid = tid >> 5, lane = tid & 31;
    int gid = lane >> 2, tig = lane & 3;
    int wm = wid >> 2, wn = wid & 3;
    int mbase = wm * 64, nbase = wn * 32;

    float acc[4][4][4];
#pragma unroll
    for (int a = 0; a < 4; a++)
#pragma unroll
        for (int b = 0; b < 4; b++)
#pragma unroll
            for (int c = 0; c < 4; c++) acc[a][b][c] = 0.0f;

    for (int kc = 0; kc < 128; kc += 64) {
        if (useXf) {
#pragma unroll
            for (int p = 0; p < 8; p++) {
                int f = tid + p * 256;
                int r = f >> 4, c4 = f & 15;
                float4 v = make_float4(0.f, 0.f, 0.f, 0.f);
                int gr = row0 + r;
                if (gr < n) v = *(const float4*)&Xf[(size_t)gr * CD + kc + c4 * 4];
                *(uint2*)&Xs[r][c4 * 4] =
                    make_uint2(pack_bf16x2(v.x, v.y), pack_bf16x2(v.z, v.w));
            }
        } else {
#pragma unroll
            for (int p = 0; p < 4; p++) {
                int f = tid + p * 256;
                int r = f >> 3, c8 = f & 7;
                uint4 v = make_uint4(0, 0, 0, 0);
                int gr = row0 + r;
                if (gr < n) v = *(const uint4*)&Hb[(size_t)gr * CD + kc + c8 * 8];
                *(uint4*)&Xs[r][c8 * 8] = v;
            }
        }
#pragma unroll
        for (int p = 0; p < 4; p++) {
            int f = tid + p * 256;
            int r = f >> 3, c8 = f & 7;
            *(uint4*)&Ws[r][c8 * 8] = *(const uint4*)&Wb[(size_t)r * CD + kc + c8 * 8];
        }
        __syncthreads();

#pragma unroll
        for (int kb = 0; kb < 64; kb += 16) {
            unsigned int af[4][4];
#pragma unroll
            for (int mt = 0; mt < 4; mt++) {
                int r = mbase + mt * 16 + gid;
                af[mt][0] = *(const unsigned int*)&Xs[r][kb + 2 * tig];
                af[mt][1] = *(const unsigned int*)&Xs[r + 8][kb + 2 * tig];
                af[mt][2] = *(const unsigned int*)&Xs[r][kb + 2 * tig + 8];
                af[mt][3] = *(const unsigned int*)&Xs[r + 8][kb + 2 * tig + 8];
            }
            unsigned int bfr[4][2];
#pragma unroll
            for (int nt = 0; nt < 4; nt++) {
                int cn = nbase + nt * 8 + gid;
                bfr[nt][0] = *(const unsigned int*)&Ws[cn][kb + 2 * tig];
                bfr[nt][1] = *(const unsigned int*)&Ws[cn][kb + 2 * tig + 8];
            }
#pragma unroll
            for (int mt = 0; mt < 4; mt++)
#pragma unroll
                for (int nt = 0; nt < 4; nt++) {
                    asm("mma.sync.aligned.m16n8k16.row.col.f32.bf16.bf16.f32 "
                        "{%0,%1,%2,%3}, {%4,%5,%6,%7}, {%8,%9}, {%0,%1,%2,%3};"
                        : "+f"(acc[mt][nt][0]), "+f"(acc[mt][nt][1]),
                          "+f"(acc[mt][nt][2]), "+f"(acc[mt][nt][3])
                        : "r"(af[mt][0]), "r"(af[mt][1]), "r"(af[mt][2]), "r"(af[mt][3]),
                          "r"(bfr[nt][0]), "r"(bfr[nt][1]));
                }
        }
        __syncthreads();
    }

    __nv_bfloat16* Pb = (__nv_bfloat16*)g_P;
#pragma unroll
    for (int mt = 0; mt < 4; mt++) {
        int r0 = row0 + mbase + mt * 16 + gid;
        int r1 = r0 + 8;
        if (outF32) {
#pragma unroll
            for (int nt = 0; nt < 4; nt++) {
                int cn = nbase + nt * 8 + tig * 2;
                if (r0 < n)
                    *(float2*)&g_P[(size_t)r0 * CD + cn] =
                        make_float2(acc[mt][nt][0], acc[mt][nt][1]);
                if (r1 < n)
                    *(float2*)&g_P[(size_t)r1 * CD + cn] =
                        make_float2(acc[mt][nt][2], acc[mt][nt][3]);
            }
        } else {
            float s0 = 1.0f, s1 = 1.0f;
            if (useDis) {
                s0 = (r0 < n) ? g_dis[r0] : 0.0f;
                s1 = (r1 < n) ? g_dis[r1] : 0.0f;
            }
#pragma unroll
            for (int nt = 0; nt < 4; nt++) {
                int cn = nbase + nt * 8 + tig * 2;
                if (r0 < n)
                    *(unsigned int*)&Pb[(size_t)r0 * CD + cn] =
                        pack_bf16x2(acc[mt][nt][0] * s0, acc[mt][nt][1] * s0);
                if (r1 < n)
                    *(unsigned int*)&Pb[(size_t)r1 * CD + cn] =
                        pack_bf16x2(acc[mt][nt][2] * s1, acc[mt][nt][3] * s1);
            }
        }
    }
}

// ---------------- gather (bf16 in, fp32 accum, bf16 out) ----------------------------
// scaleRows=1: P holds raw h'; multiply each gathered row by g_dis[row] (conv1).
// scaleRows=0: P already pre-scaled by dis (conv2).
__global__ void k_gather(const float* __restrict__ bias, int scaleRows, int n) {
    int w = (blockIdx.x * blockDim.x + threadIdx.x) >> 5;
    if (w >= n) return;
    int lane = threadIdx.x & 31;

    const uint2* __restrict__ P2 = (const uint2*)g_P;
    float sw = g_dis[w];
    float selfS = scaleRows ? sw : 1.0f;

    uint2 sv = P2[(size_t)w * 32 + lane];
    float ax = selfS * __low2float(*(__nv_bfloat162*)&sv.x);
    float ay = selfS * __high2float(*(__nv_bfloat162*)&sv.x);
    float az = selfS * __low2float(*(__nv_bfloat162*)&sv.y);
    float aw = selfS * __high2float(*(__nv_bfloat162*)&sv.y);

    int o = g_off[w];
    int c = g_cnt[w];
    int j = 0;
    for (; j + 4 <= c; j += 4) {
        int r0 = g_bkt[o + j];
        int r1 = g_bkt[o + j + 1];
        int r2 = g_bkt[o + j + 2];
        int r3 = g_bkt[o + j + 3];
        float s0 = scaleRows ? g_dis[r0] : 1.0f;
        float s1 = scaleRows ? g_dis[r1] : 1.0f;
        float s2 = scaleRows ? g_dis[r2] : 1.0f;
        float s3 = scaleRows ? g_dis[r3] : 1.0f;
        uint2 v0 = P2[(size_t)r0 * 32 + lane];
        uint2 v1 = P2[(size_t)r1 * 32 + lane];
        uint2 v2 = P2[(size_t)r2 * 32 + lane];
        uint2 v3 = P2[(size_t)r3 * 32 + lane];
        ax = fmaf(s0, __low2float(*(__nv_bfloat162*)&v0.x), ax);
        ay = fmaf(s0, __high2float(*(__nv_bfloat162*)&v0.x), ay);
        az = fmaf(s0, __low2float(*(__nv_bfloat162*)&v0.y), az);
        aw = fmaf(s0, __high2float(*(__nv_bfloat162*)&v0.y), aw);
        ax = fmaf(s1, __low2float(*(__nv_bfloat162*)&v1.x), ax);
        ay = fmaf(s1, __high2float(*(__nv_bfloat162*)&v1.x), ay);
        az = fmaf(s1, __low2float(*(__nv_bfloat162*)&v1.y), az);
        aw = fmaf(s1, __high2float(*(__nv_bfloat162*)&v1.y), aw);
        ax = fmaf(s2, __low2float(*(__nv_bfloat162*)&v2.x), ax);
        ay = fmaf(s2, __high2float(*(__nv_bfloat162*)&v2.x), ay);
        az = fmaf(s2, __low2float(*(__nv_bfloat162*)&v2.y), az);
        aw = fmaf(s2, __high2float(*(__nv_bfloat162*)&v2.y), aw);
        ax = fmaf(s3, __low2float(*(__nv_bfloat162*)&v3.x), ax);
        ay = fmaf(s3, __high2float(*(__nv_bfloat162*)&v3.x), ay);
        az = fmaf(s3, __low2float(*(__nv_bfloat162*)&v3.y), az);
        aw = fmaf(s3, __high2float(*(__nv_bfloat162*)&v3.y), aw);
    }
    for (; j < c; j++) {
        int r0 = g_bkt[o + j];
        float s0 = scaleRows ? g_dis[r0] : 1.0f;
        uint2 v0 = P2[(size_t)r0 * 32 + lane];
        ax = fmaf(s0, __low2float(*(__nv_bfloat162*)&v0.x), ax);
        ay = fmaf(s0, __high2float(*(__nv_bfloat162*)&v0.x), ay);
        az = fmaf(s0, __low2float(*(__nv_bfloat162*)&v0.y), az);
        aw = fmaf(s0, __high2float(*(__nv_bfloat162*)&v0.y), aw);
    }

    float4 b = *(const float4*)&bias[lane * 4];
    float ox = fmaxf(fmaf(ax, sw, b.x), 0.0f);
    float oy = fmaxf(fmaf(ay, sw, b.y), 0.0f);
    float oz = fmaxf(fmaf(az, sw, b.z), 0.0f);
    float ow = fmaxf(fmaf(aw, sw, b.w), 0.0f);
    ((uint2*)g_H)[(size_t)w * 32 + lane] =
        make_uint2(pack_bf16x2(ox, oy), pack_bf16x2(oz, ow));
}

// ---------------- log_softmax (fp32) ----------------
__global__ void k_logsoftmax(const float* __restrict__ bl, float* __restrict__ out, int n) {
    int w = (blockIdx.x * blockDim.x + threadIdx.x) >> 5;
    if (w >= n) return;
    int lane = threadIdx.x & 31;

    float4 v = *(const float4*)&g_P[(size_t)w * CD + lane * 4];
    float4 b = *(const float4*)&bl[lane * 4];
    v.x += b.x; v.y += b.y; v.z += b.z; v.w += b.w;

    float m = fmaxf(fmaxf(v.x, v.y), fmaxf(v.z, v.w));
#pragma unroll
    for (int d = 16; d; d >>= 1) m = fmaxf(m, __shfl_xor_sync(0xFFFFFFFFu, m, d));

    float s = expf(v.x - m) + expf(v.y - m) + expf(v.z - m) + expf(v.w - m);
#pragma unroll
    for (int d = 16; d; d >>= 1) s += __shfl_xor_sync(0xFFFFFFFFu, s, d);

    float l = m + logf(s);
    float4 o = make_float4(v.x - l, v.y - l, v.z - l, v.w - l);
    *(float4*)&out[(size_t)w * CD + lane * 4] = o;
}

// ---------------- launch ----------------
extern "C" void kernel_launch(void* const* d_in, const int* in_sizes, int n_in,
                              void* d_out, int out_size) {
    const float* x  = (const float*)d_in[0];
    const int*   ei = (const int*)d_in[1];
    const float* W1 = (const float*)d_in[2];
    const float* b1 = (const float*)d_in[3];
    const float* W2 = (const float*)d_in[4];
    const float* b2 = (const float*)d_in[5];
    const float* Wl = (const float*)d_in[6];
    const float* bl = (const float*)d_in[7];

    int n = in_sizes[0] / CD;
    int E = in_sizes[1] / 2;
    const int* row = ei;
    const int* col = ei + E;

    int nb256 = (n + 255) / 256;
    int nbScan = (n + 1023) / 1024;
    int gatherB = (n + 7) / 8;
    int gemmB = (n + 127) / 128;
    int countB = 512;

    // init: zero counts + convert weights
    k_init<<<nb256, 256>>>(W1, W2, Wl, n);

    // conv1 GEMM (raw output, no dis dependence) overlapped with degree count
    k_gemm_bf16<<<gemmB + countB, 256>>>(x, 1, 0, 0, 0, n, gemmB, col, E);

    // scan + bucket fill
    k_scan1<<<nbScan, 1024>>>(n);
    k_scan2<<<1, 128>>>(nbScan);
    k_scan3<<<nb256, 256>>>(n);
    k_fill<<<2048, 256>>>(row, col, E);

    // conv1 aggregate (applies dis per gathered row + output)
    k_gather<<<gatherB, 256>>>(b1, 1, n);

    // conv2 (pre-scaled epilogue, gather mode 0)
    k_gemm_bf16<<<gemmB, 256>>>(nullptr, 0, 1, 1, 0, n, gemmB, nullptr, 0);
    k_gather<<<gatherB, 256>>>(b2, 0, n);

    // linear (fp32 out) + log_softmax
    k_gemm_bf16<<<gemmB, 256>>>(nullptr, 0, 2, 0, 1, n, gemmB, nullptr, 0);
    k_logsoftmax<<<gatherB, 256>>>(bl, (float*)d_out, n);
}

// round 10
// speedup vs baseline: 1.0166x; 1.0166x over previous
#include <cuda_runtime.h>
#include <cuda_bf16.h>
#include <stdint.h>
#include <math.h>

#define CD 128
#define NMAX 100352
#define EMAX 1700000

// ---------------- device scratch ----------------
__device__ __align__(16) float g_P[(size_t)NMAX * CD];      // fp32 logits OR bf16 conv out
__device__ __align__(16) float g_H[(size_t)NMAX * CD / 2];  // bf16 hidden
__device__ float g_dis[NMAX];
__device__ int   g_cnt[NMAX];
__device__ int   g_off[NMAX];
__device__ int   g_cur[NMAX];
__device__ int   g_bkt[EMAX];
__device__ int   g_part[128];
__device__ __align__(16) __nv_bfloat16 g_Wb[3][CD * CD];    // bf16 W[c_out][c_in]

__device__ __forceinline__ unsigned int pack_bf16x2(float lo, float hi) {
    unsigned int r;
    asm("cvt.rn.bf16x2.f32 %0, %1, %2;" : "=r"(r) : "f"(hi), "f"(lo));
    return r;
}

// ---------------- init: zero cnt + convert all three weights ----------------
__global__ void k_init(const float* __restrict__ W1, const float* __restrict__ W2,
                       const float* __restrict__ Wl, int n) {
    int i = blockIdx.x * blockDim.x + threadIdx.x;
    if (i < n) g_cnt[i] = 0;
    if (i < 3 * 16384) {
        int which = i >> 14, j = i & 16383;
        const float* W = (which == 0) ? W1 : (which == 1) ? W2 : Wl;
        g_Wb[which][j] = __float2bfloat16(W[j]);
    }
}

__global__ void k_count(const int* __restrict__ col, int E) {
    for (int e = blockIdx.x * blockDim.x + threadIdx.x; e < E;
         e += gridDim.x * blockDim.x)
        atomicAdd(&g_cnt[col[e]], 1);
}

// ---------------- scan pass 1 (dis fused): per-block exclusive scan + partials ------
__global__ void k_scan1(int n) {
    __shared__ int wsum[32];
    int tid = threadIdx.x;
    int lane = tid & 31, wid = tid >> 5;
    int i = blockIdx.x * 1024 + tid;
    int x = (i < n) ? g_cnt[i] : 0;
    if (i < n) g_dis[i] = rsqrtf((float)x + 1.0f);
    int v = x;
#pragma unroll
    for (int d = 1; d < 32; d <<= 1) {
        int t = __shfl_up_sync(0xFFFFFFFFu, v, d);
        if (lane >= d) v += t;
    }
    if (lane == 31) wsum[wid] = v;
    __syncthreads();
    if (wid == 0) {
        int w = wsum[lane];
#pragma unroll
        for (int d = 1; d < 32; d <<= 1) {
            int t = __shfl_up_sync(0xFFFFFFFFu, w, d);
            if (lane >= d) w += t;
        }
        wsum[lane] = w;
    }
    __syncthreads();
    int base = (wid > 0) ? wsum[wid - 1] : 0;
    if (i < n) g_off[i] = base + v - x;
    if (tid == 1023) g_part[blockIdx.x] = wsum[31];
}

// ---------------- scan pass 2+3 merged: each block redundantly scans partials -------
__global__ void k_scan23(int nbScan, int n) {
    __shared__ int s[128];
    int tid = threadIdx.x;
    int lane = tid & 31, w = tid >> 5;

    if (tid < 128) {
        int x = (tid < nbScan) ? g_part[tid] : 0;
        int v = x;
#pragma unroll
        for (int d = 1; d < 32; d <<= 1) {
            int t = __shfl_up_sync(0xFFFFFFFFu, v, d);
            if (lane >= d) v += t;
        }
        s[tid] = v;              // inclusive within warp (x still in reg)
    }
    __syncthreads();
    int add = 0;
    if (tid < 128) {
        for (int ww = 0; ww < w; ww++) add += s[ww * 32 + 31];
    }
    __syncthreads();
    if (tid < 128) {
        int x = (tid < nbScan) ? g_part[tid] : 0;
        s[tid] = s[tid] + add - x;   // exclusive prefix of partials
    }
    __syncthreads();

    int i = blockIdx.x * blockDim.x + tid;
    if (i < n) {
        int v = g_off[i] + s[i >> 10];
        g_off[i] = v;
        g_cur[i] = v;
    }
}

// ---------------- bf16 tensor-core GEMM (+optional fill tail blocks) ----------------
// Blocks [0, gemmB): P[i][c] = scale? * sum_k X[i][k] * W[c][k]  (m16n8k16 bf16 MMA)
// Blocks [gemmB, gridDim): grid-stride bucket fill over edges (conv1 launch only;
// independent of the GEMM — fill needs off/cur from scan, GEMM needs dis from scan).
__global__ void __launch_bounds__(256)
k_gemm_bf16(const float* __restrict__ Xf, int useXf, int widx, int outF32, int n,
            int gemmB, const int* __restrict__ rowE, const int* __restrict__ colE,
            int E) {
    if (blockIdx.x >= gemmB) {          // fill-mode tail blocks (overlapped preproc)
        int nb = gridDim.x - gemmB;
        for (int e = (blockIdx.x - gemmB) * blockDim.x + threadIdx.x; e < E;
             e += nb * blockDim.x) {
            int p = atomicAdd(&g_cur[colE[e]], 1);
            g_bkt[p] = rowE[e];
        }
        return;
    }

    __shared__ __align__(16) __nv_bfloat16 Xs[128][72];
    __shared__ __align__(16) __nv_bfloat16 Ws[128][72];

    const __nv_bfloat16* __restrict__ Hb = (const __nv_bfloat16*)g_H;
    const __nv_bfloat16* __restrict__ Wb = g_Wb[widx];

    int row0 = blockIdx.x * 128;
    int tid = threadIdx.x;
    int wid = tid >> 5, lane = tid & 31;
    int gid = lane >> 2, tig = lane & 3;
    int wm = wid >> 2, wn = wid & 3;
    int mbase = wm * 64, nbase = wn * 32;

    float acc[4][4][4];
#pragma unroll
    for (int a = 0; a < 4; a++)
#pragma unroll
        for (int b = 0; b < 4; b++)
#pragma unroll
            for (int c = 0; c < 4; c++) acc[a][b][c] = 0.0f;

    for (int kc = 0; kc < 128; kc += 64) {
        if (useXf) {
#pragma unroll
            for (int p = 0; p < 8; p++) {
                int f = tid + p * 256;
                int r = f >> 4, c4 = f & 15;
                float4 v = make_float4(0.f, 0.f, 0.f, 0.f);
                int gr = row0 + r;
                if (gr < n) v = *(const float4*)&Xf[(size_t)gr * CD + kc + c4 * 4];
                *(uint2*)&Xs[r][c4 * 4] =
                    make_uint2(pack_bf16x2(v.x, v.y), pack_bf16x2(v.z, v.w));
            }
        } else {
#pragma unroll
            for (int p = 0; p < 4; p++) {
                int f = tid + p * 256;
                int r = f >> 3, c8 = f & 7;
                uint4 v = make_uint4(0, 0, 0, 0);
                int gr = row0 + r;
                if (gr < n) v = *(const uint4*)&Hb[(size_t)gr * CD + kc + c8 * 8];
                *(uint4*)&Xs[r][c8 * 8] = v;
            }
        }
#pragma unroll
        for (int p = 0; p < 4; p++) {
            int f = tid + p * 256;
            int r = f >> 3, c8 = f & 7;
            *(uint4*)&Ws[r][c8 * 8] = *(const uint4*)&Wb[(size_t)r * CD + kc + c8 * 8];
        }
        __syncthreads();

#pragma unroll
        for (int kb = 0; kb < 64; kb += 16) {
            unsigned int af[4][4];
#pragma unroll
            for (int mt = 0; mt < 4; mt++) {
                int r = mbase + mt * 16 + gid;
                af[mt][0] = *(const unsigned int*)&Xs[r][kb + 2 * tig];
                af[mt][1] = *(const unsigned int*)&Xs[r + 8][kb + 2 * tig];
                af[mt][2] = *(const unsigned int*)&Xs[r][kb + 2 * tig + 8];
                af[mt][3] = *(const unsigned int*)&Xs[r + 8][kb + 2 * tig + 8];
            }
            unsigned int bfr[4][2];
#pragma unroll
            for (int nt = 0; nt < 4; nt++) {
                int cn = nbase + nt * 8 + gid;
                bfr[nt][0] = *(const unsigned int*)&Ws[cn][kb + 2 * tig];
                bfr[nt][1] = *(const unsigned int*)&Ws[cn][kb + 2 * tig + 8];
            }
#pragma unroll
            for (int mt = 0; mt < 4; mt++)
#pragma unroll
                for (int nt = 0; nt < 4; nt++) {
                    asm("mma.sync.aligned.m16n8k16.row.col.f32.bf16.bf16.f32 "
                        "{%0,%1,%2,%3}, {%4,%5,%6,%7}, {%8,%9}, {%0,%1,%2,%3};"
                        : "+f"(acc[mt][nt][0]), "+f"(acc[mt][nt][1]),
                          "+f"(acc[mt][nt][2]), "+f"(acc[mt][nt][3])
                        : "r"(af[mt][0]), "r"(af[mt][1]), "r"(af[mt][2]), "r"(af[mt][3]),
                          "r"(bfr[nt][0]), "r"(bfr[nt][1]));
                }
        }
        __syncthreads();
    }

    __nv_bfloat16* Pb = (__nv_bfloat16*)g_P;
#pragma unroll
    for (int mt = 0; mt < 4; mt++) {
        int r0 = row0 + mbase + mt * 16 + gid;
        int r1 = r0 + 8;
        if (outF32) {
#pragma unroll
            for (int nt = 0; nt < 4; nt++) {
                int cn = nbase + nt * 8 + tig * 2;
                if (r0 < n)
                    *(float2*)&g_P[(size_t)r0 * CD + cn] =
                        make_float2(acc[mt][nt][0], acc[mt][nt][1]);
                if (r1 < n)
                    *(float2*)&g_P[(size_t)r1 * CD + cn] =
                        make_float2(acc[mt][nt][2], acc[mt][nt][3]);
            }
        } else {
            float s0 = (r0 < n) ? g_dis[r0] : 0.0f;
            float s1 = (r1 < n) ? g_dis[r1] : 0.0f;
#pragma unroll
            for (int nt = 0; nt < 4; nt++) {
                int cn = nbase + nt * 8 + tig * 2;
                if (r0 < n)
                    *(unsigned int*)&Pb[(size_t)r0 * CD + cn] =
                        pack_bf16x2(acc[mt][nt][0] * s0, acc[mt][nt][1] * s0);
                if (r1 < n)
                    *(unsigned int*)&Pb[(size_t)r1 * CD + cn] =
                        pack_bf16x2(acc[mt][nt][2] * s1, acc[mt][nt][3] * s1);
            }
        }
    }
}

// ---------------- gather (bf16 in, fp32 accum, bf16 out; P pre-scaled by dis) -------
__global__ void k_gather(const float* __restrict__ bias, int n) {
    int w = (blockIdx.x * blockDim.x + threadIdx.x) >> 5;
    if (w >= n) return;
    int lane = threadIdx.x & 31;

    const uint2* __restrict__ P2 = (const uint2*)g_P;
    uint2 sv = P2[(size_t)w * 32 + lane];
    float ax = __low2float(*(__nv_bfloat162*)&sv.x);
    float ay = __high2float(*(__nv_bfloat162*)&sv.x);
    float az = __low2float(*(__nv_bfloat162*)&sv.y);
    float aw = __high2float(*(__nv_bfloat162*)&sv.y);

    int o = g_off[w];
    int c = g_cnt[w];
    int j = 0;
    for (; j + 4 <= c; j += 4) {
        int r0 = g_bkt[o + j];
        int r1 = g_bkt[o + j + 1];
        int r2 = g_bkt[o + j + 2];
        int r3 = g_bkt[o + j + 3];
        uint2 v0 = P2[(size_t)r0 * 32 + lane];
        uint2 v1 = P2[(size_t)r1 * 32 + lane];
        uint2 v2 = P2[(size_t)r2 * 32 + lane];
        uint2 v3 = P2[(size_t)r3 * 32 + lane];
        ax += __low2float(*(__nv_bfloat162*)&v0.x);
        ay += __high2float(*(__nv_bfloat162*)&v0.x);
        az += __low2float(*(__nv_bfloat162*)&v0.y);
        aw += __high2float(*(__nv_bfloat162*)&v0.y);
        ax += __low2float(*(__nv_bfloat162*)&v1.x);
        ay += __high2float(*(__nv_bfloat162*)&v1.x);
        az += __low2float(*(__nv_bfloat162*)&v1.y);
        aw += __high2float(*(__nv_bfloat162*)&v1.y);
        ax += __low2float(*(__nv_bfloat162*)&v2.x);
        ay += __high2float(*(__nv_bfloat162*)&v2.x);
        az += __low2float(*(__nv_bfloat162*)&v2.y);
        aw += __high2float(*(__nv_bfloat162*)&v2.y);
        ax += __low2float(*(__nv_bfloat162*)&v3.x);
        ay += __high2float(*(__nv_bfloat162*)&v3.x);
        az += __low2float(*(__nv_bfloat162*)&v3.y);
        aw += __high2float(*(__nv_bfloat162*)&v3.y);
    }
    for (; j < c; j++) {
        int r0 = g_bkt[o + j];
        uint2 v0 = P2[(size_t)r0 * 32 + lane];
        ax += __low2float(*(__nv_bfloat162*)&v0.x);
        ay += __high2float(*(__nv_bfloat162*)&v0.x);
        az += __low2float(*(__nv_bfloat162*)&v0.y);
        aw += __high2float(*(__nv_bfloat162*)&v0.y);
    }

    float s = g_dis[w];
    float4 b = *(const float4*)&bias[lane * 4];
    float ox = fmaxf(fmaf(ax, s, b.x), 0.0f);
    float oy = fmaxf(fmaf(ay, s, b.y), 0.0f);
    float oz = fmaxf(fmaf(az, s, b.z), 0.0f);
    float ow = fmaxf(fmaf(aw, s, b.w), 0.0f);
    ((uint2*)g_H)[(size_t)w * 32 + lane] =
        make_uint2(pack_bf16x2(ox, oy), pack_bf16x2(oz, ow));
}

// ---------------- log_softmax (fp32) ----------------
__global__ void k_logsoftmax(const float* __restrict__ bl, float* __restrict__ out, int n) {
    int w = (blockIdx.x * blockDim.x + threadIdx.x) >> 5;
    if (w >= n) return;
    int lane = threadIdx.x & 31;

    float4 v = *(const float4*)&g_P[(size_t)w * CD + lane * 4];
    float4 b = *(const float4*)&bl[lane * 4];
    v.x += b.x; v.y += b.y; v.z += b.z; v.w += b.w;

    float m = fmaxf(fmaxf(v.x, v.y), fmaxf(v.z, v.w));
#pragma unroll
    for (int d = 16; d; d >>= 1) m = fmaxf(m, __shfl_xor_sync(0xFFFFFFFFu, m, d));

    float s = expf(v.x - m) + expf(v.y - m) + expf(v.z - m) + expf(v.w - m);
#pragma unroll
    for (int d = 16; d; d >>= 1) s += __shfl_xor_sync(0xFFFFFFFFu, s, d);

    float l = m + logf(s);
    float4 o = make_float4(v.x - l, v.y - l, v.z - l, v.w - l);
    *(float4*)&out[(size_t)w * CD + lane * 4] = o;
}

// ---------------- launch ----------------
extern "C" void kernel_launch(void* const* d_in, const int* in_sizes, int n_in,
                              void* d_out, int out_size) {
    const float* x  = (const float*)d_in[0];
    const int*   ei = (const int*)d_in[1];
    const float* W1 = (const float*)d_in[2];
    const float* b1 = (const float*)d_in[3];
    const float* W2 = (const float*)d_in[4];
    const float* b2 = (const float*)d_in[5];
    const float* Wl = (const float*)d_in[6];
    const float* bl = (const float*)d_in[7];

    int n = in_sizes[0] / CD;
    int E = in_sizes[1] / 2;
    const int* row = ei;
    const int* col = ei + E;

    int nb256 = (n + 255) / 256;
    int nbScan = (n + 1023) / 1024;
    int gatherB = (n + 7) / 8;
    int gemmB = (n + 127) / 128;
    int fillB = 512;

    // init: zero counts + convert weights
    k_init<<<nb256, 256>>>(W1, W2, Wl, n);

    // degree count + scan (dis fused into scan1; scan2 merged into scan23)
    k_count<<<2048, 256>>>(col, E);
    k_scan1<<<nbScan, 1024>>>(n);
    k_scan23<<<nb256, 256>>>(nbScan, n);

    // conv1 GEMM (pre-scaled epilogue) overlapped with bucket fill (fat kernel)
    k_gemm_bf16<<<gemmB + fillB, 256>>>(x, 1, 0, 0, n, gemmB, row, col, E);
    k_gather<<<gatherB, 256>>>(b1, n);

    // conv2
    k_gemm_bf16<<<gemmB, 256>>>(nullptr, 0, 1, 0, n, gemmB, nullptr, nullptr, 0);
    k_gather<<<gatherB, 256>>>(b2, n);

    // linear (fp32 out) + log_softmax
    k_gemm_bf16<<<gemmB, 256>>>(nullptr, 0, 2, 1, n, gemmB, nullptr, nullptr, 0);
    k_logsoftmax<<<gatherB, 256>>>(bl, (float*)d_out, n);
}

// round 11
// speedup vs baseline: 1.0735x; 1.0560x over previous
#include <cuda_runtime.h>
#include <cuda_bf16.h>
#include <stdint.h>
#include <math.h>

#define CD 128
#define NMAX 100352
#define EMAX 1700000

// ---------------- device scratch ----------------
__device__ __align__(16) float g_P[(size_t)NMAX * CD];      // fp32 logits OR bf16 conv out
__device__ __align__(16) float g_H[(size_t)NMAX * CD / 2];  // bf16 hidden
__device__ float g_dis[NMAX];
__device__ int   g_cnt[NMAX];
__device__ int   g_off[NMAX];
__device__ int   g_cur[NMAX];
__device__ int   g_bkt[EMAX];
__device__ int   g_part[128];
__device__ __align__(16) __nv_bfloat16 g_Wb[3][CD * CD];    // bf16 W[c_out][c_in]

__device__ __forceinline__ unsigned int pack_bf16x2(float lo, float hi) {
    unsigned int r;
    asm("cvt.rn.bf16x2.f32 %0, %1, %2;" : "=r"(r) : "f"(hi), "f"(lo));
    return r;
}

// ---------------- init: zero cnt + convert all three weights ----------------
__global__ void k_init(const float* __restrict__ W1, const float* __restrict__ W2,
                       const float* __restrict__ Wl, int n) {
    int i = blockIdx.x * blockDim.x + threadIdx.x;
    if (i < n) g_cnt[i] = 0;
    if (i < 3 * 16384) {
        int which = i >> 14, j = i & 16383;
        const float* W = (which == 0) ? W1 : (which == 1) ? W2 : Wl;
        g_Wb[which][j] = __float2bfloat16(W[j]);
    }
}

__global__ void k_count(const int* __restrict__ col, int E) {
    for (int e = blockIdx.x * blockDim.x + threadIdx.x; e < E;
         e += gridDim.x * blockDim.x)
        atomicAdd(&g_cnt[col[e]], 1);
}

// ---------------- scan pass 1 (dis fused): per-block exclusive scan + partials ------
__global__ void k_scan1(int n) {
    __shared__ int wsum[32];
    int tid = threadIdx.x;
    int lane = tid & 31, wid = tid >> 5;
    int i = blockIdx.x * 1024 + tid;
    int x = (i < n) ? g_cnt[i] : 0;
    if (i < n) g_dis[i] = rsqrtf((float)x + 1.0f);
    int v = x;
#pragma unroll
    for (int d = 1; d < 32; d <<= 1) {
        int t = __shfl_up_sync(0xFFFFFFFFu, v, d);
        if (lane >= d) v += t;
    }
    if (lane == 31) wsum[wid] = v;
    __syncthreads();
    if (wid == 0) {
        int w = wsum[lane];
#pragma unroll
        for (int d = 1; d < 32; d <<= 1) {
            int t = __shfl_up_sync(0xFFFFFFFFu, w, d);
            if (lane >= d) w += t;
        }
        wsum[lane] = w;
    }
    __syncthreads();
    int base = (wid > 0) ? wsum[wid - 1] : 0;
    if (i < n) g_off[i] = base + v - x;
    if (tid == 1023) g_part[blockIdx.x] = wsum[31];
}

// ---------------- scan pass 2+3 merged: each block redundantly scans partials -------
__global__ void k_scan23(int nbScan, int n) {
    __shared__ int s[128];
    int tid = threadIdx.x;
    int lane = tid & 31, w = tid >> 5;

    if (tid < 128) {
        int x = (tid < nbScan) ? g_part[tid] : 0;
        int v = x;
#pragma unroll
        for (int d = 1; d < 32; d <<= 1) {
            int t = __shfl_up_sync(0xFFFFFFFFu, v, d);
            if (lane >= d) v += t;
        }
        s[tid] = v;              // inclusive within warp
    }
    __syncthreads();
    int add = 0;
    if (tid < 128) {
        for (int ww = 0; ww < w; ww++) add += s[ww * 32 + 31];
    }
    __syncthreads();
    if (tid < 128) {
        int x = (tid < nbScan) ? g_part[tid] : 0;
        s[tid] = s[tid] + add - x;   // exclusive prefix of partials
    }
    __syncthreads();

    int i = blockIdx.x * blockDim.x + tid;
    if (i < n) {
        int v = g_off[i] + s[i >> 10];
        g_off[i] = v;
        g_cur[i] = v;
    }
}

__global__ void k_fill(const int* __restrict__ row, const int* __restrict__ col, int E) {
    for (int e = blockIdx.x * blockDim.x + threadIdx.x; e < E;
         e += gridDim.x * blockDim.x) {
        int p = atomicAdd(&g_cur[col[e]], 1);
        g_bkt[p] = row[e];
    }
}

// ---------------- bf16 tensor-core GEMM (R4-exact) ----------------------------------
// P[i][c] = scale? * sum_k X[i][k] * W[c][k]; 128x128 tile, 256 thr, m16n8k16.
__global__ void __launch_bounds__(256)
k_gemm_bf16(const float* __restrict__ Xf, int useXf, int widx, int outF32, int n) {
    __shared__ __align__(16) __nv_bfloat16 Xs[128][72];
    __shared__ __align__(16) __nv_bfloat16 Ws[128][72];

    const __nv_bfloat16* __restrict__ Hb = (const __nv_bfloat16*)g_H;
    const __nv_bfloat16* __restrict__ Wb = g_Wb[widx];

    int row0 = blockIdx.x * 128;
    int tid = threadIdx.x;
    int wid = tid >> 5, lane = tid & 31;
    int gid = lane >> 2, tig = lane & 3;
    int wm = wid >> 2, wn = wid & 3;
    int mbase = wm * 64, nbase = wn * 32;

    float acc[4][4][4];
#pragma unroll
    for (int a = 0; a < 4; a++)
#pragma unroll
        for (int b = 0; b < 4; b++)
#pragma unroll
            for (int c = 0; c < 4; c++) acc[a][b][c] = 0.0f;

    for (int kc = 0; kc < 128; kc += 64) {
        if (useXf) {
#pragma unroll
            for (int p = 0; p < 8; p++) {
                int f = tid + p * 256;
                int r = f >> 4, c4 = f & 15;
                float4 v = make_float4(0.f, 0.f, 0.f, 0.f);
                int gr = row0 + r;
                if (gr < n) v = *(const float4*)&Xf[(size_t)gr * CD + kc + c4 * 4];
                *(uint2*)&Xs[r][c4 * 4] =
                    make_uint2(pack_bf16x2(v.x, v.y), pack_bf16x2(v.z, v.w));
            }
        } else {
#pragma unroll
            for (int p = 0; p < 4; p++) {
                int f = tid + p * 256;
                int r = f >> 3, c8 = f & 7;
                uint4 v = make_uint4(0, 0, 0, 0);
                int gr = row0 + r;
                if (gr < n) v = *(const uint4*)&Hb[(size_t)gr * CD + kc + c8 * 8];
                *(uint4*)&Xs[r][c8 * 8] = v;
            }
        }
#pragma unroll
        for (int p = 0; p < 4; p++) {
            int f = tid + p * 256;
            int r = f >> 3, c8 = f & 7;
            *(uint4*)&Ws[r][c8 * 8] = *(const uint4*)&Wb[(size_t)r * CD + kc + c8 * 8];
        }
        __syncthreads();

#pragma unroll
        for (int kb = 0; kb < 64; kb += 16) {
            unsigned int af[4][4];
#pragma unroll
            for (int mt = 0; mt < 4; mt++) {
                int r = mbase + mt * 16 + gid;
                af[mt][0] = *(const unsigned int*)&Xs[r][kb + 2 * tig];
                af[mt][1] = *(const unsigned int*)&Xs[r + 8][kb + 2 * tig];
                af[mt][2] = *(const unsigned int*)&Xs[r][kb + 2 * tig + 8];
                af[mt][3] = *(const unsigned int*)&Xs[r + 8][kb + 2 * tig + 8];
            }
            unsigned int bfr[4][2];
#pragma unroll
            for (int nt = 0; nt < 4; nt++) {
                int cn = nbase + nt * 8 + gid;
                bfr[nt][0] = *(const unsigned int*)&Ws[cn][kb + 2 * tig];
                bfr[nt][1] = *(const unsigned int*)&Ws[cn][kb + 2 * tig + 8];
            }
#pragma unroll
            for (int mt = 0; mt < 4; mt++)
#pragma unroll
                for (int nt = 0; nt < 4; nt++) {
                    asm("mma.sync.aligned.m16n8k16.row.col.f32.bf16.bf16.f32 "
                        "{%0,%1,%2,%3}, {%4,%5,%6,%7}, {%8,%9}, {%0,%1,%2,%3};"
                        : "+f"(acc[mt][nt][0]), "+f"(acc[mt][nt][1]),
                          "+f"(acc[mt][nt][2]), "+f"(acc[mt][nt][3])
                        : "r"(af[mt][0]), "r"(af[mt][1]), "r"(af[mt][2]), "r"(af[mt][3]),
                          "r"(bfr[nt][0]), "r"(bfr[nt][1]));
                }
        }
        __syncthreads();
    }

    __nv_bfloat16* Pb = (__nv_bfloat16*)g_P;
#pragma unroll
    for (int mt = 0; mt < 4; mt++) {
        int r0 = row0 + mbase + mt * 16 + gid;
        int r1 = r0 + 8;
        if (outF32) {
#pragma unroll
            for (int nt = 0; nt < 4; nt++) {
                int cn = nbase + nt * 8 + tig * 2;
                if (r0 < n)
                    *(float2*)&g_P[(size_t)r0 * CD + cn] =
                        make_float2(acc[mt][nt][0], acc[mt][nt][1]);
                if (r1 < n)
                    *(float2*)&g_P[(size_t)r1 * CD + cn] =
                        make_float2(acc[mt][nt][2], acc[mt][nt][3]);
            }
        } else {
            float s0 = (r0 < n) ? g_dis[r0] : 0.0f;
            float s1 = (r1 < n) ? g_dis[r1] : 0.0f;
#pragma unroll
            for (int nt = 0; nt < 4; nt++) {
                int cn = nbase + nt * 8 + tig * 2;
                if (r0 < n)
                    *(unsigned int*)&Pb[(size_t)r0 * CD + cn] =
                        pack_bf16x2(acc[mt][nt][0] * s0, acc[mt][nt][1] * s0);
                if (r1 < n)
                    *(unsigned int*)&Pb[(size_t)r1 * CD + cn] =
                        pack_bf16x2(acc[mt][nt][2] * s1, acc[mt][nt][3] * s1);
            }
        }
    }
}

// ---------------- gather (R4-exact: bf16 in, fp32 accum, bf16 out) ------------------
__global__ void k_gather(const float* __restrict__ bias, int n) {
    int w = (blockIdx.x * blockDim.x + threadIdx.x) >> 5;
    if (w >= n) return;
    int lane = threadIdx.x & 31;

    const uint2* __restrict__ P2 = (const uint2*)g_P;
    uint2 sv = P2[(size_t)w * 32 + lane];
    float ax = __low2float(*(__nv_bfloat162*)&sv.x);
    float ay = __high2float(*(__nv_bfloat162*)&sv.x);
    float az = __low2float(*(__nv_bfloat162*)&sv.y);
    float aw = __high2float(*(__nv_bfloat162*)&sv.y);

    int o = g_off[w];
    int c = g_cnt[w];
    int j = 0;
    for (; j + 2 <= c; j += 2) {
        int r0 = g_bkt[o + j];
        int r1 = g_bkt[o + j + 1];
        uint2 v0 = P2[(size_t)r0 * 32 + lane];
        uint2 v1 = P2[(size_t)r1 * 32 + lane];
        ax += __low2float(*(__nv_bfloat162*)&v0.x);
        ay += __high2float(*(__nv_bfloat162*)&v0.x);
        az += __low2float(*(__nv_bfloat162*)&v0.y);
        aw += __high2float(*(__nv_bfloat162*)&v0.y);
        ax += __low2float(*(__nv_bfloat162*)&v1.x);
        ay += __high2float(*(__nv_bfloat162*)&v1.x);
        az += __low2float(*(__nv_bfloat162*)&v1.y);
        aw += __high2float(*(__nv_bfloat162*)&v1.y);
    }
    if (j < c) {
        int r0 = g_bkt[o + j];
        uint2 v0 = P2[(size_t)r0 * 32 + lane];
        ax += __low2float(*(__nv_bfloat162*)&v0.x);
        ay += __high2float(*(__nv_bfloat162*)&v0.x);
        az += __low2float(*(__nv_bfloat162*)&v0.y);
        aw += __high2float(*(__nv_bfloat162*)&v0.y);
    }

    float s = g_dis[w];
    float4 b = *(const float4*)&bias[lane * 4];
    float ox = fmaxf(fmaf(ax, s, b.x), 0.0f);
    float oy = fmaxf(fmaf(ay, s, b.y), 0.0f);
    float oz = fmaxf(fmaf(az, s, b.z), 0.0f);
    float ow = fmaxf(fmaf(aw, s, b.w), 0.0f);
    ((uint2*)g_H)[(size_t)w * 32 + lane] =
        make_uint2(pack_bf16x2(ox, oy), pack_bf16x2(oz, ow));
}

// ---------------- log_softmax (fp32) ----------------
__global__ void k_logsoftmax(const float* __restrict__ bl, float* __restrict__ out, int n) {
    int w = (blockIdx.x * blockDim.x + threadIdx.x) >> 5;
    if (w >= n) return;
    int lane = threadIdx.x & 31;

    float4 v = *(const float4*)&g_P[(size_t)w * CD + lane * 4];
    float4 b = *(const float4*)&bl[lane * 4];
    v.x += b.x; v.y += b.y; v.z += b.z; v.w += b.w;

    float m = fmaxf(fmaxf(v.x, v.y), fmaxf(v.z, v.w));
#pragma unroll
    for (int d = 16; d; d >>= 1) m = fmaxf(m, __shfl_xor_sync(0xFFFFFFFFu, m, d));

    float s = expf(v.x - m) + expf(v.y - m) + expf(v.z - m) + expf(v.w - m);
#pragma unroll
    for (int d = 16; d; d >>= 1) s += __shfl_xor_sync(0xFFFFFFFFu, s, d);

    float l = m + logf(s);
    float4 o = make_float4(v.x - l, v.y - l, v.z - l, v.w - l);
    *(float4*)&out[(size_t)w * CD + lane * 4] = o;
}

// ---------------- launch ----------------
extern "C" void kernel_launch(void* const* d_in, const int* in_sizes, int n_in,
                              void* d_out, int out_size) {
    const float* x  = (const float*)d_in[0];
    const int*   ei = (const int*)d_in[1];
    const float* W1 = (const float*)d_in[2];
    const float* b1 = (const float*)d_in[3];
    const float* W2 = (const float*)d_in[4];
    const float* b2 = (const float*)d_in[5];
    const float* Wl = (const float*)d_in[6];
    const float* bl = (const float*)d_in[7];

    int n = in_sizes[0] / CD;
    int E = in_sizes[1] / 2;
    const int* row = ei;
    const int* col = ei + E;

    int nb256 = (n + 255) / 256;
    int nbScan = (n + 1023) / 1024;
    int gatherB = (n + 7) / 8;
    int gemmB = (n + 127) / 128;

    // init: zero counts + convert weights
    k_init<<<nb256, 256>>>(W1, W2, Wl, n);

    // degree + bucketing (all standalone, wide launches)
    k_count<<<2048, 256>>>(col, E);
    k_scan1<<<nbScan, 1024>>>(n);
    k_scan23<<<nb256, 256>>>(nbScan, n);
    k_fill<<<2048, 256>>>(row, col, E);

    // conv1
    k_gemm_bf16<<<gemmB, 256>>>(x, 1, 0, 0, n);
    k_gather<<<gatherB, 256>>>(b1, n);

    // conv2
    k_gemm_bf16<<<gemmB, 256>>>(nullptr, 0, 1, 0, n);
    k_gather<<<gatherB, 256>>>(b2, n);

    // linear (fp32 out) + log_softmax
    k_gemm_bf16<<<gemmB, 256>>>(nullptr, 0, 2, 1, n);
    k_logsoftmax<<<gatherB, 256>>>(bl, (float*)d_out, n);
}